// round 13
// baseline (speedup 1.0000x reference)
#include <cuda_runtime.h>
#include <math.h>

typedef unsigned long long u64;

// Problem constants (fixed shapes)
#define BATCH 128
#define TT    32
#define DD    128
#define HH    256
#define OO    128
#define ZZ    384   // D + H

#define NTHREADS 512
#define NWARPS   16    // rows per block (1 row per warp, fixed for all t)
#define NB       16    // batches per block
#define NRES     8     // SMEM-resident batches per warp
#define NREG     2     // register-resident batches per warp (3 broke ptxas)
#define NSTRM0   (NRES + NREG)     // first streamed batch index (10)
#define NROWG    16    // 256 rows / 16
#define NBATG    8     // 128 batches / 16
#define NBLOCKS  (NROWG * NBATG)   // 128 blocks; 1 per SM (single wave)

#define FSTR16 ((HH * ZZ) / 4)   // 16-byte units between consecutive batches in F

// Dynamic SMEM: z staging (16 x 96 float4) + resident F (16 warps x 8 x 96)
#define Z_F4     (NB * 96)                  // 1536
#define FSH_F4   (NWARPS * NRES * 96)       // 12288
#define SMEM_BYTES ((Z_F4 + FSH_F4) * 16)   // 221184 (<= 227KB opt-in)

__device__ float g_hbuf[2][BATCH * HH];
__device__ unsigned int g_bar[NBATG * 32];

// ---- packed f32x2 helpers ----
__device__ __forceinline__ u64 fma2_(u64 a, u64 b, u64 c) {
    u64 d; asm("fma.rn.f32x2 %0, %1, %2, %3;" : "=l"(d) : "l"(a), "l"(b), "l"(c)); return d;
}
__device__ __forceinline__ u64 add2_(u64 a, u64 b) {
    u64 d; asm("add.rn.f32x2 %0, %1, %2;" : "=l"(d) : "l"(a), "l"(b)); return d;
}
__device__ __forceinline__ u64 mul2_(u64 a, u64 b) {
    u64 d; asm("mul.rn.f32x2 %0, %1, %2;" : "=l"(d) : "l"(a), "l"(b)); return d;
}

__device__ __forceinline__ float warp_sum(float v) {
    v += __shfl_xor_sync(0xffffffffu, v, 16);
    v += __shfl_xor_sync(0xffffffffu, v, 8);
    v += __shfl_xor_sync(0xffffffffu, v, 4);
    v += __shfl_xor_sync(0xffffffffu, v, 2);
    v += __shfl_xor_sync(0xffffffffu, v, 1);
    return v;
}

__device__ __forceinline__ float fast_tanh(float x) {
    float xc = fminf(fmaxf(x, -9.0f), 9.0f);
    float e  = __expf(2.0f * xc);
    return __fdividef(e - 1.0f, e + 1.0f);
}

// load/store 6 packed u64 (= 12 floats/lane = one 384-wide row slice)
__device__ __forceinline__ void ld6(u64* d, const ulonglong2* p, int lane) {
    ulonglong2 a = p[lane], b = p[lane + 32], c = p[lane + 64];
    d[0] = a.x; d[1] = a.y; d[2] = b.x; d[3] = b.y; d[4] = c.x; d[5] = c.y;
}
__device__ __forceinline__ void st6(ulonglong2* p, int lane, const u64* d) {
    p[lane]      = make_ulonglong2(d[0], d[1]);
    p[lane + 32] = make_ulonglong2(d[2], d[3]);
    p[lane + 64] = make_ulonglong2(d[4], d[5]);
}

// fused STPN cell: dot + tanh + Hebbian update (in f); returns h
__device__ __forceinline__ float cell_compute(const u64* w, const u64* l, const u64* g,
                                              float bi, u64* f, const u64* z) {
    u64 acc = mul2_(add2_(w[0], f[0]), z[0]);
    #pragma unroll
    for (int k = 1; k < 6; k++) acc = fma2_(add2_(w[k], f[k]), z[k], acc);
    float lo, hi;
    asm("mov.b64 {%0, %1}, %2;" : "=f"(lo), "=f"(hi) : "l"(acc));
    const float dot = warp_sum(lo + hi);
    const float hn = fast_tanh(dot + bi);
    u64 hn2; asm("mov.b64 %0, {%1, %1};" : "=l"(hn2) : "f"(hn));
    #pragma unroll
    for (int k = 0; k < 6; k++)
        f[k] = fma2_(l[k], f[k], mul2_(g[k], mul2_(hn2, z[k])));
    return hn;
}

__global__ __launch_bounds__(NTHREADS, 1)
void stpn_persistent(const float4* __restrict__ x4,   // [B,T,D]
                     const float4* __restrict__ h04,  // [B,H]
                     const float*  __restrict__ F0,   // [B,H,Z]
                     float* F_out,                    // [B,H,Z]
                     const float* __restrict__ W,     // [H,Z]
                     const float* __restrict__ bias,  // [H]
                     const float* __restrict__ lam,   // [H,Z]
                     const float* __restrict__ gam,   // [H,Z]
                     float* __restrict__ h_out)       // [B,H]
{
    extern __shared__ __align__(16) float4 smem[];
    float4* zsh4 = smem;                                          // [NB][96]
    ulonglong2* fsh = reinterpret_cast<ulonglong2*>(smem + Z_F4); // [NWARPS][NRES][96]
    __shared__ __align__(16) float hsh[NB][NWARPS];               // per-step h tile

    const int tid  = threadIdx.x;
    const int warp = tid >> 5;
    const int lane = tid & 31;
    const int rowg = blockIdx.x & (NROWG - 1);
    const int batg = blockIdx.x >> 4;
    const int r    = rowg * NWARPS + warp;
    const int b0   = batg * NB;

    // Slow-weight params for this warp's row: loaded ONCE for the whole run
    u64 w[6], l[6], g[6];
    ld6(w, reinterpret_cast<const ulonglong2*>(W   + (size_t)r * ZZ), lane);
    ld6(l, reinterpret_cast<const ulonglong2*>(lam + (size_t)r * ZZ), lane);
    ld6(g, reinterpret_cast<const ulonglong2*>(gam + (size_t)r * ZZ), lane);
    const float bi = bias[r];

    const size_t fbase = ((size_t)b0 * HH + r) * (ZZ / 4);        // 16B units
    ulonglong2* Fw2 = reinterpret_cast<ulonglong2*>(F_out) + fbase;
    const ulonglong2* F02 = reinterpret_cast<const ulonglong2*>(F0) + fbase;
    ulonglong2* myfsh = fsh + (size_t)(warp * NRES) * 96;

    // ---- prologue: preload SMEM-resident batches from F0 ----
    #pragma unroll
    for (int js = 0; js < NRES; js++) {
        const ulonglong2* src = F02 + (size_t)js * FSTR16;
        ulonglong2* dst = myfsh + js * 96;
        dst[lane]      = src[lane];
        dst[lane + 32] = src[lane + 32];
        dst[lane + 64] = src[lane + 64];
    }
    // ---- register-resident batches (live for the entire run) ----
    u64 fr0[6], fr1[6];
    ld6(fr0, F02 + (size_t)(NRES + 0) * FSTR16, lane);
    ld6(fr1, F02 + (size_t)(NRES + 1) * FSTR16, lane);

    // first streamed batch for t=0, prefetched before the loop
    u64 fn[6];
    ld6(fn, F02 + (size_t)NSTRM0 * FSTR16, lane);

    // stage x-part of z for t = 0
    for (int i = tid; i < NB * 32; i += NTHREADS) {
        int j = i >> 5, c = i & 31;
        zsh4[j * 96 + c] = x4[((size_t)(b0 + j) * TT + 0) * 32 + c];
    }

    unsigned int* ctr = &g_bar[batg * 32];

    for (int t = 0; t < TT; t++) {
        const bool last = (t == TT - 1);
        const ulonglong2* Fr2 = (t == 0) ? F02 : (const ulonglong2*)Fw2;

        // stage h-part of z (barrier-dependent)
        {
            const float4* hp4 = (t == 0) ? h04
                              : reinterpret_cast<const float4*>(g_hbuf[(t - 1) & 1]);
            for (int i = tid; i < NB * 64; i += NTHREADS) {
                int j = i >> 6, c = i & 63;
                zsh4[j * 96 + 32 + c] = __ldcg(&hp4[(size_t)(b0 + j) * 64 + c]);
            }
        }
        __syncthreads();

        // ---- SMEM-resident batches — streamed prefetch already in flight ----
        #pragma unroll
        for (int js = 0; js < NRES; js++) {
            ulonglong2* sa = myfsh + js * 96;
            u64 f[6], z[6];
            ld6(f, sa, lane);
            ld6(z, reinterpret_cast<const ulonglong2*>(zsh4 + js * 96), lane);
            const float hn = cell_compute(w, l, g, bi, f, z);
            if (!last) st6(sa, lane, f);
            else       st6(Fw2 + (size_t)js * FSTR16, lane, f);
            if (lane == 0) hsh[js][warp] = hn;
        }

        // ---- register-resident batches (no F memory traffic at all) ----
        {
            u64 z[6];
            ld6(z, reinterpret_cast<const ulonglong2*>(zsh4 + (NRES + 0) * 96), lane);
            const float hn = cell_compute(w, l, g, bi, fr0, z);
            if (lane == 0) hsh[NRES + 0][warp] = hn;
            if (last) st6(Fw2 + (size_t)(NRES + 0) * FSTR16, lane, fr0);
        }
        {
            u64 z[6];
            ld6(z, reinterpret_cast<const ulonglong2*>(zsh4 + (NRES + 1) * 96), lane);
            const float hn = cell_compute(w, l, g, bi, fr1, z);
            if (lane == 0) hsh[NRES + 1][warp] = hn;
            if (last) st6(Fw2 + (size_t)(NRES + 1) * FSTR16, lane, fr1);
        }

        // ---- streamed batches, pipelined (F stores never fenced) ----
        #pragma unroll 1
        for (int j = NSTRM0; j < NB; j++) {
            u64 f[6], z[6];
            #pragma unroll
            for (int k = 0; k < 6; k++) f[k] = fn[k];
            if (j < NB - 1) ld6(fn, Fr2 + (size_t)(j + 1) * FSTR16, lane);
            ld6(z, reinterpret_cast<const ulonglong2*>(zsh4 + j * 96), lane);
            const float hn = cell_compute(w, l, g, bi, f, z);
            st6(Fw2 + (size_t)j * FSTR16, lane, f);
            if (lane == 0) hsh[j][warp] = hn;
        }

        // prefetch NEXT step's first streamed batch BEFORE the barrier:
        // reads this warp's own F data written above (same-thread program
        // order => visible, no fence needed); overlaps the barrier spin.
        if (!last) ld6(fn, Fw2 + (size_t)NSTRM0 * FSTR16, lane);

        __syncthreads();   // hsh complete (block-scope ordering, HW-native)

        // ---- warp 0: publish h tile (1 KB, the only fenced stores);
        //      warps 1-15: stage x(t+1) ----
        if (warp == 0) {
            float* dst = last ? h_out : g_hbuf[t & 1];
            #pragma unroll
            for (int k = 0; k < 2; k++) {
                const int s = lane + 32 * k;   // 0..63 float4 stores
                const int j = s >> 2;          // batch
                const int q = s & 3;           // quarter of the 16-row tile
                float4 v = make_float4(hsh[j][q * 4 + 0], hsh[j][q * 4 + 1],
                                       hsh[j][q * 4 + 2], hsh[j][q * 4 + 3]);
                *reinterpret_cast<float4*>(
                    &dst[(size_t)(b0 + j) * HH + rowg * NWARPS + q * 4]) = v;
            }
            if (!last) {
                asm volatile("membar.gl;" ::: "memory");   // warp 0's stores only
                if (lane == 0) {
                    atomicAdd(ctr, 1u);
                    const unsigned int target = (unsigned int)(t + 1) * NROWG;
                    unsigned int cur;
                    do {
                        asm volatile("ld.acquire.gpu.u32 %0, [%1];"
                                     : "=r"(cur) : "l"(ctr));
                        if (cur < target) __nanosleep(32);
                    } while (cur < target);
                }
            }
        } else if (!last) {
            for (int i = tid - 32; i < NB * 32; i += (NTHREADS - 32)) {
                int j = i >> 5, c = i & 31;
                zsh4[j * 96 + c] = x4[((size_t)(b0 + j) * TT + (t + 1)) * 32 + c];
            }
        }
        if (last) break;
        __syncthreads();
    }
}

// tag_space = h_final @ W_out^T + b_out — warp per (batch, output) [proven]
__global__ __launch_bounds__(128)
void tag_head_kernel(const float4* __restrict__ h4,    // [B,H]
                     const float4* __restrict__ Wout4, // [O,H]
                     const float*  __restrict__ bout,  // [O]
                     float* __restrict__ tag)          // [B,O]
{
    const int warp = threadIdx.x >> 5;
    const int lane = threadIdx.x & 31;
    const int o = blockIdx.x * 4 + warp;
    const int b = blockIdx.y;

    const float4* hr = h4    + (size_t)b * (HH / 4);
    const float4* wr = Wout4 + (size_t)o * (HH / 4);
    float4 hv0 = hr[lane], hv1 = hr[lane + 32];
    float4 wv0 = wr[lane], wv1 = wr[lane + 32];

    float dot = hv0.x * wv0.x + hv0.y * wv0.y + hv0.z * wv0.z + hv0.w * wv0.w
              + hv1.x * wv1.x + hv1.y * wv1.y + hv1.z * wv1.z + hv1.w * wv1.w;
    dot = warp_sum(dot);
    if (lane == 0) tag[(size_t)b * OO + o] = dot + bout[o];
}

extern "C" void kernel_launch(void* const* d_in, const int* in_sizes, int n_in,
                              void* d_out, int out_size)
{
    const float* x     = (const float*)d_in[0];
    const float* h0    = (const float*)d_in[1];
    const float* F0    = (const float*)d_in[2];
    const float* W     = (const float*)d_in[3];
    const float* bias  = (const float*)d_in[4];
    const float* lam   = (const float*)d_in[5];
    const float* gam   = (const float*)d_in[6];
    const float* Wout  = (const float*)d_in[7];
    const float* bout  = (const float*)d_in[8];

    // Output layout: concat(tag_space [B,O], h [B,H], F [B,H,Z])
    float* out   = (float*)d_out;
    float* tag   = out;
    float* h_out = out + (size_t)BATCH * OO;
    float* F_out = out + (size_t)BATCH * OO + (size_t)BATCH * HH;

    (void)cudaFuncSetAttribute(stpn_persistent,
                               cudaFuncAttributeMaxDynamicSharedMemorySize,
                               SMEM_BYTES);

    void* bar_ptr = nullptr;
    cudaGetSymbolAddress(&bar_ptr, g_bar);
    cudaMemsetAsync(bar_ptr, 0, sizeof(unsigned int) * NBATG * 32);

    stpn_persistent<<<NBLOCKS, NTHREADS, SMEM_BYTES>>>(
        (const float4*)x, (const float4*)h0, F0, F_out,
        W, bias, lam, gam, h_out);

    dim3 tg(OO / 4, BATCH);
    tag_head_kernel<<<tg, 128>>>((const float4*)h_out, (const float4*)Wout,
                                 bout, tag);
}

// round 14
// speedup vs baseline: 1.0498x; 1.0498x over previous
#include <cuda_runtime.h>
#include <math.h>

typedef unsigned long long u64;

// Problem constants (fixed shapes)
#define BATCH 128
#define TT    32
#define DD    128
#define HH    256
#define OO    128
#define ZZ    384   // D + H

#define NTHREADS 512
#define NWARPS   16    // rows per block (1 row per warp, fixed for all t)
#define NB       16    // batches per block
#define NRES     8     // SMEM-resident batches per warp
#define NREG     2     // register-resident batches per warp
#define NSTRM0   (NRES + NREG)     // first streamed batch index (10)
#define NROWG    16    // 256 rows / 16
#define NBATG    8     // 128 batches / 16
#define NBLOCKS  (NROWG * NBATG)   // 128 blocks; 1 per SM (single wave)

#define FSTR16 ((HH * ZZ) / 4)   // 16-byte units between consecutive batches in F

// Dynamic SMEM: z staging (16 x 96 float4) + resident F (16 warps x 8 x 96)
#define Z_F4     (NB * 96)                  // 1536
#define FSH_F4   (NWARPS * NRES * 96)       // 12288
#define SMEM_BYTES ((Z_F4 + FSH_F4) * 16)   // 221184 (<= 227KB opt-in)

__device__ float g_hbuf[2][BATCH * HH];
__device__ unsigned int g_bar[NBATG * 32];

// ---- packed f32x2 helpers ----
__device__ __forceinline__ u64 fma2_(u64 a, u64 b, u64 c) {
    u64 d; asm("fma.rn.f32x2 %0, %1, %2, %3;" : "=l"(d) : "l"(a), "l"(b), "l"(c)); return d;
}
__device__ __forceinline__ u64 add2_(u64 a, u64 b) {
    u64 d; asm("add.rn.f32x2 %0, %1, %2;" : "=l"(d) : "l"(a), "l"(b)); return d;
}
__device__ __forceinline__ u64 mul2_(u64 a, u64 b) {
    u64 d; asm("mul.rn.f32x2 %0, %1, %2;" : "=l"(d) : "l"(a), "l"(b)); return d;
}

__device__ __forceinline__ float warp_sum(float v) {
    v += __shfl_xor_sync(0xffffffffu, v, 16);
    v += __shfl_xor_sync(0xffffffffu, v, 8);
    v += __shfl_xor_sync(0xffffffffu, v, 4);
    v += __shfl_xor_sync(0xffffffffu, v, 2);
    v += __shfl_xor_sync(0xffffffffu, v, 1);
    return v;
}

__device__ __forceinline__ float fast_tanh(float x) {
    float xc = fminf(fmaxf(x, -9.0f), 9.0f);
    float e  = __expf(2.0f * xc);
    return __fdividef(e - 1.0f, e + 1.0f);
}

// load/store 6 packed u64 (= 12 floats/lane = one 384-wide row slice)
__device__ __forceinline__ void ld6(u64* d, const ulonglong2* p, int lane) {
    ulonglong2 a = p[lane], b = p[lane + 32], c = p[lane + 64];
    d[0] = a.x; d[1] = a.y; d[2] = b.x; d[3] = b.y; d[4] = c.x; d[5] = c.y;
}
__device__ __forceinline__ void st6(ulonglong2* p, int lane, const u64* d) {
    p[lane]      = make_ulonglong2(d[0], d[1]);
    p[lane + 32] = make_ulonglong2(d[2], d[3]);
    p[lane + 64] = make_ulonglong2(d[4], d[5]);
}

// fused STPN cell: dot + tanh + Hebbian update (in f); returns h
__device__ __forceinline__ float cell_compute(const u64* w, const u64* l, const u64* g,
                                              float bi, u64* f, const u64* z) {
    u64 acc = mul2_(add2_(w[0], f[0]), z[0]);
    #pragma unroll
    for (int k = 1; k < 6; k++) acc = fma2_(add2_(w[k], f[k]), z[k], acc);
    float lo, hi;
    asm("mov.b64 {%0, %1}, %2;" : "=f"(lo), "=f"(hi) : "l"(acc));
    const float dot = warp_sum(lo + hi);
    const float hn = fast_tanh(dot + bi);
    u64 hn2; asm("mov.b64 %0, {%1, %1};" : "=l"(hn2) : "f"(hn));
    #pragma unroll
    for (int k = 0; k < 6; k++)
        f[k] = fma2_(l[k], f[k], mul2_(g[k], mul2_(hn2, z[k])));
    return hn;
}

__global__ __launch_bounds__(NTHREADS, 1)
void stpn_persistent(const float4* __restrict__ x4,   // [B,T,D]
                     const float4* __restrict__ h04,  // [B,H]
                     const float*  __restrict__ F0,   // [B,H,Z]
                     float* F_out,                    // [B,H,Z]
                     const float* __restrict__ W,     // [H,Z]
                     const float* __restrict__ bias,  // [H]
                     const float* __restrict__ lam,   // [H,Z]
                     const float* __restrict__ gam,   // [H,Z]
                     float* __restrict__ h_out)       // [B,H]
{
    extern __shared__ __align__(16) float4 smem[];
    float4* zsh4 = smem;                                          // [NB][96]
    ulonglong2* fsh = reinterpret_cast<ulonglong2*>(smem + Z_F4); // [NWARPS][NRES][96]
    __shared__ __align__(16) float hsh[NB][NWARPS];               // per-step h tile

    const int tid  = threadIdx.x;
    const int warp = tid >> 5;
    const int lane = tid & 31;
    const int rowg = blockIdx.x & (NROWG - 1);
    const int batg = blockIdx.x >> 4;
    const int r    = rowg * NWARPS + warp;
    const int b0   = batg * NB;

    // Slow-weight params for this warp's row: loaded ONCE for the whole run
    u64 w[6], l[6], g[6];
    ld6(w, reinterpret_cast<const ulonglong2*>(W   + (size_t)r * ZZ), lane);
    ld6(l, reinterpret_cast<const ulonglong2*>(lam + (size_t)r * ZZ), lane);
    ld6(g, reinterpret_cast<const ulonglong2*>(gam + (size_t)r * ZZ), lane);
    const float bi = bias[r];

    const size_t fbase = ((size_t)b0 * HH + r) * (ZZ / 4);        // 16B units
    ulonglong2* Fw2 = reinterpret_cast<ulonglong2*>(F_out) + fbase;
    const ulonglong2* F02 = reinterpret_cast<const ulonglong2*>(F0) + fbase;
    ulonglong2* myfsh = fsh + (size_t)(warp * NRES) * 96;

    // ---- prologue: preload SMEM-resident batches from F0 ----
    #pragma unroll
    for (int js = 0; js < NRES; js++) {
        const ulonglong2* src = F02 + (size_t)js * FSTR16;
        ulonglong2* dst = myfsh + js * 96;
        dst[lane]      = src[lane];
        dst[lane + 32] = src[lane + 32];
        dst[lane + 64] = src[lane + 64];
    }
    // ---- register-resident batches (live for the entire run) ----
    u64 fr0[6], fr1[6];
    ld6(fr0, F02 + (size_t)(NRES + 0) * FSTR16, lane);
    ld6(fr1, F02 + (size_t)(NRES + 1) * FSTR16, lane);

    // stage x-part of z for t = 0
    for (int i = tid; i < NB * 32; i += NTHREADS) {
        int j = i >> 5, c = i & 31;
        zsh4[j * 96 + c] = x4[((size_t)(b0 + j) * TT + 0) * 32 + c];
    }

    unsigned int* ctr = &g_bar[batg * 32];

    for (int t = 0; t < TT; t++) {
        const bool last = (t == TT - 1);
        const ulonglong2* Fr2 = (t == 0) ? F02 : (const ulonglong2*)Fw2;

        // prefetch first streamed batch (warp-private, no barrier dependency)
        u64 fn[6];
        ld6(fn, Fr2 + (size_t)NSTRM0 * FSTR16, lane);

        // stage h-part of z (barrier-dependent)
        {
            const float4* hp4 = (t == 0) ? h04
                              : reinterpret_cast<const float4*>(g_hbuf[(t - 1) & 1]);
            for (int i = tid; i < NB * 64; i += NTHREADS) {
                int j = i >> 6, c = i & 63;
                zsh4[j * 96 + 32 + c] = __ldcg(&hp4[(size_t)(b0 + j) * 64 + c]);
            }
        }
        __syncthreads();

        // cell executors ------------------------------------------------
        auto do_res = [&](int js) {
            ulonglong2* sa = myfsh + js * 96;
            u64 f[6], z[6];
            ld6(f, sa, lane);
            ld6(z, reinterpret_cast<const ulonglong2*>(zsh4 + js * 96), lane);
            const float hn = cell_compute(w, l, g, bi, f, z);
            if (!last) st6(sa, lane, f);
            else       st6(Fw2 + (size_t)js * FSTR16, lane, f);
            if (lane == 0) hsh[js][warp] = hn;
        };
        auto do_reg = [&](u64* frq, int jb) {
            u64 z[6];
            ld6(z, reinterpret_cast<const ulonglong2*>(zsh4 + jb * 96), lane);
            const float hn = cell_compute(w, l, g, bi, frq, z);
            if (lane == 0) hsh[jb][warp] = hn;
            if (last) st6(Fw2 + (size_t)jb * FSTR16, lane, frq);
        };
        auto do_strm = [&](int j, int jnext) {
            u64 f[6], z[6];
            #pragma unroll
            for (int k = 0; k < 6; k++) f[k] = fn[k];
            if (jnext >= 0) ld6(fn, Fr2 + (size_t)jnext * FSTR16, lane);  // issue early
            ld6(z, reinterpret_cast<const ulonglong2*>(zsh4 + j * 96), lane);
            const float hn = cell_compute(w, l, g, bi, f, z);
            st6(Fw2 + (size_t)j * FSTR16, lane, f);
            if (lane == 0) hsh[j][warp] = hn;
        };

        // interleaved schedule: R R S R R S R R S R R S G S G S
        // each streamed load issues ~3 cell-slots (~750 cyc) before use,
        // overlapping L2 latency/traffic with SMEM-resident work.
        do_res(0); do_res(1);
        do_strm(10, 11);
        do_res(2); do_res(3);
        do_strm(11, 12);
        do_res(4); do_res(5);
        do_strm(12, 13);
        do_res(6); do_res(7);
        do_strm(13, 14);
        do_reg(fr0, 8);
        do_strm(14, 15);
        do_reg(fr1, 9);
        do_strm(15, -1);

        __syncthreads();   // hsh complete (block-scope ordering, HW-native)

        // ---- warp 0: publish h tile (1 KB, the only fenced stores);
        //      warps 1-15: stage x(t+1) ----
        if (warp == 0) {
            float* dst = last ? h_out : g_hbuf[t & 1];
            #pragma unroll
            for (int k = 0; k < 2; k++) {
                const int s = lane + 32 * k;   // 0..63 float4 stores
                const int j = s >> 2;          // batch
                const int q = s & 3;           // quarter of the 16-row tile
                float4 v = make_float4(hsh[j][q * 4 + 0], hsh[j][q * 4 + 1],
                                       hsh[j][q * 4 + 2], hsh[j][q * 4 + 3]);
                *reinterpret_cast<float4*>(
                    &dst[(size_t)(b0 + j) * HH + rowg * NWARPS + q * 4]) = v;
            }
            if (!last) {
                asm volatile("membar.gl;" ::: "memory");   // warp 0's stores only
                if (lane == 0) {
                    atomicAdd(ctr, 1u);
                    const unsigned int target = (unsigned int)(t + 1) * NROWG;
                    unsigned int cur;
                    do {
                        asm volatile("ld.acquire.gpu.u32 %0, [%1];"
                                     : "=r"(cur) : "l"(ctr));
                        if (cur < target) __nanosleep(32);
                    } while (cur < target);
                }
            }
        } else if (!last) {
            for (int i = tid - 32; i < NB * 32; i += (NTHREADS - 32)) {
                int j = i >> 5, c = i & 31;
                zsh4[j * 96 + c] = x4[((size_t)(b0 + j) * TT + (t + 1)) * 32 + c];
            }
        }
        if (last) break;
        __syncthreads();
    }
}

// tag_space = h_final @ W_out^T + b_out — warp per (batch, output) [proven]
__global__ __launch_bounds__(128)
void tag_head_kernel(const float4* __restrict__ h4,    // [B,H]
                     const float4* __restrict__ Wout4, // [O,H]
                     const float*  __restrict__ bout,  // [O]
                     float* __restrict__ tag)          // [B,O]
{
    const int warp = threadIdx.x >> 5;
    const int lane = threadIdx.x & 31;
    const int o = blockIdx.x * 4 + warp;
    const int b = blockIdx.y;

    const float4* hr = h4    + (size_t)b * (HH / 4);
    const float4* wr = Wout4 + (size_t)o * (HH / 4);
    float4 hv0 = hr[lane], hv1 = hr[lane + 32];
    float4 wv0 = wr[lane], wv1 = wr[lane + 32];

    float dot = hv0.x * wv0.x + hv0.y * wv0.y + hv0.z * wv0.z + hv0.w * wv0.w
              + hv1.x * wv1.x + hv1.y * wv1.y + hv1.z * wv1.z + hv1.w * wv1.w;
    dot = warp_sum(dot);
    if (lane == 0) tag[(size_t)b * OO + o] = dot + bout[o];
}

extern "C" void kernel_launch(void* const* d_in, const int* in_sizes, int n_in,
                              void* d_out, int out_size)
{
    const float* x     = (const float*)d_in[0];
    const float* h0    = (const float*)d_in[1];
    const float* F0    = (const float*)d_in[2];
    const float* W     = (const float*)d_in[3];
    const float* bias  = (const float*)d_in[4];
    const float* lam   = (const float*)d_in[5];
    const float* gam   = (const float*)d_in[6];
    const float* Wout  = (const float*)d_in[7];
    const float* bout  = (const float*)d_in[8];

    // Output layout: concat(tag_space [B,O], h [B,H], F [B,H,Z])
    float* out   = (float*)d_out;
    float* tag   = out;
    float* h_out = out + (size_t)BATCH * OO;
    float* F_out = out + (size_t)BATCH * OO + (size_t)BATCH * HH;

    (void)cudaFuncSetAttribute(stpn_persistent,
                               cudaFuncAttributeMaxDynamicSharedMemorySize,
                               SMEM_BYTES);

    void* bar_ptr = nullptr;
    cudaGetSymbolAddress(&bar_ptr, g_bar);
    cudaMemsetAsync(bar_ptr, 0, sizeof(unsigned int) * NBATG * 32);

    stpn_persistent<<<NBLOCKS, NTHREADS, SMEM_BYTES>>>(
        (const float4*)x, (const float4*)h0, F0, F_out,
        W, bias, lam, gam, h_out);

    dim3 tg(OO / 4, BATCH);
    tag_head_kernel<<<tg, 128>>>((const float4*)h_out, (const float4*)Wout,
                                 bout, tag);
}